// round 12
// baseline (speedup 1.0000x reference)
#include <cuda_runtime.h>
#include <cuda_fp16.h>
#include <math.h>
#include <cstdint>

#define BB 4
#define SS 2048
#define DD 512
#define HH 8
#define BH (BB*HH)
#define BSN (BB*SS)

// ---------------- scratch (device globals; fp16x2 words) --------------------
__device__ unsigned g_qhw[(size_t)BH*SS*32];   // [bh, s, 32w]
__device__ unsigned g_khw[(size_t)BH*SS*32];
__device__ unsigned g_vhw[(size_t)BH*SS*32];
__device__ unsigned g_ohw[(size_t)BH*SS*32];
__device__ unsigned g_wtw[4*(size_t)DD*(DD/2)]; // W^T fp16x2, [n][k/2]
__device__ float    g_y[(size_t)BSN*DD];

// ---------------- helpers -----------------------------------------------------
__device__ __forceinline__ unsigned fppack(float lo, float hi) {
    __half2 h = __floats2half2_rn(lo, hi);
    return *reinterpret_cast<unsigned*>(&h);
}

__device__ __forceinline__ void mma_fp16(float c[4], unsigned a0, unsigned a1,
        unsigned a2, unsigned a3, unsigned b0, unsigned b1) {
    asm("mma.sync.aligned.m16n8k16.row.col.f32.f16.f16.f32 "
        "{%0,%1,%2,%3},{%4,%5,%6,%7},{%8,%9},{%0,%1,%2,%3};"
        : "+f"(c[0]), "+f"(c[1]), "+f"(c[2]), "+f"(c[3])
        : "r"(a0), "r"(a1), "r"(a2), "r"(a3), "r"(b0), "r"(b1));
}

__device__ __forceinline__ float fexp2(float x) {
    float y;
    asm("ex2.approx.f32 %0, %1;" : "=f"(y) : "f"(x));
    return y;
}
__device__ __forceinline__ float flog2(float x) {
    float y;
    asm("lg2.approx.f32 %0, %1;" : "=f"(y) : "f"(x));
    return y;
}
#define EXP_C 0.18033688011112042f   // log2(e)/8

// ---------------- kernel 0: transpose W -> fp16 (Wt[n][k] = W[k][n]) --------
__global__ __launch_bounds__(256) void wtrans_kernel(const float* __restrict__ Wq,
        const float* __restrict__ Wk, const float* __restrict__ Wv,
        const float* __restrict__ Wo) {
    __shared__ float tile[32][33];
    const float* W = (blockIdx.z == 0) ? Wq : (blockIdx.z == 1) ? Wk
                   : (blockIdx.z == 2) ? Wv : Wo;
    unsigned* T = g_wtw + (size_t)blockIdx.z * DD * (DD/2);
    const int x0 = blockIdx.x * 32, y0 = blockIdx.y * 32;
    const int tx = threadIdx.x & 31, ty = threadIdx.x >> 5;   // 32 x 8
    #pragma unroll
    for (int i = 0; i < 32; i += 8)
        tile[ty + i][tx] = W[(size_t)(y0 + ty + i) * DD + x0 + tx];
    __syncthreads();
    const int wc0 = threadIdx.x & 7, xx = threadIdx.x >> 3;   // 8 wc x 32 xx
    #pragma unroll
    for (int i = 0; i < 16; i += 8) {
        int wc = wc0 + i;
        T[(size_t)(x0 + xx) * (DD/2) + (y0 >> 1) + wc] =
            fppack(tile[2*wc][xx], tile[2*wc + 1][xx]);
    }
}

// ---------------- kernel 1: QKV projection (fp16 mma, 512 thr) ---------------
#define PJ_SMEM (2*128*36*4)

__global__ __launch_bounds__(512, 2) void proj_kernel(const float* __restrict__ q,
        const float* __restrict__ k, const float* __restrict__ v) {
    extern __shared__ unsigned ps[];
    unsigned* Ah = ps;              // [128][36] fp16x2 (X rows)
    unsigned* Bh = Ah + 128*36;     // [128][36] (Wt rows = output cols)

    const float* X; unsigned* Y;
    if (blockIdx.z == 0)      { X = q; Y = g_qhw; }
    else if (blockIdx.z == 1) { X = k; Y = g_khw; }
    else                      { X = v; Y = g_vhw; }
    const unsigned* Wt = g_wtw + (size_t)blockIdx.z * DD * (DD/2);

    const int row0 = blockIdx.y * 128, col0 = blockIdx.x * 128;
    const int tid = threadIdx.x, lane = tid & 31, warp = tid >> 5;
    const int g = lane >> 2, t = lane & 3;
    const int wm = warp & 7, wn = warp >> 3;   // 8 x 2

    const int fr = tid >> 3;            // 0..63
    const int fcb = (tid & 7) << 3;
    const int fw = fcb >> 1;

    float acc[8][4] = {};

    for (int c = 0; c < 8; c++) {
        const int k0 = c * 64, kw0 = c * 32;
        __syncthreads();
        #pragma unroll
        for (int sw = 0; sw < 2; sw++) {
            int r = fr + sw * 64;
            {   // A = X rows (fp32 -> fp16)
                const float* src = X + (size_t)(row0 + r) * DD + k0 + fcb;
                float4 v0 = *(const float4*)src;
                float4 v1 = *(const float4*)(src + 4);
                *(uint4*)(Ah + r*36 + fw) = make_uint4(
                    fppack(v0.x, v0.y), fppack(v0.z, v0.w),
                    fppack(v1.x, v1.y), fppack(v1.z, v1.w));
            }
            *(uint4*)(Bh + r*36 + fw) =
                *(const uint4*)(Wt + (size_t)(col0 + r) * (DD/2) + kw0 + fw);
        }
        __syncthreads();
        #pragma unroll
        for (int s = 0; s < 4; s++) {
            const int kw = s * 8;
            int r = wm * 16 + g;
            unsigned a0 = Ah[r*36 + kw + t],     a1 = Ah[(r+8)*36 + kw + t];
            unsigned a2 = Ah[r*36 + kw + t + 4], a3 = Ah[(r+8)*36 + kw + t + 4];
            #pragma unroll
            for (int nt = 0; nt < 8; nt++) {
                int cc = wn * 64 + nt * 8 + g;
                unsigned b0 = Bh[cc*36 + kw + t], b1 = Bh[cc*36 + kw + t + 4];
                mma_fp16(acc[nt], a0, a1, a2, a3, b0, b1);
            }
        }
    }
    const int bidx = row0 >> 11;
    {
        int r0 = row0 + wm * 16 + g;
        int s0 = r0 & 2047;
        #pragma unroll
        for (int nt = 0; nt < 8; nt++) {
            int col = col0 + wn * 64 + nt * 8 + 2 * t;
            int h = col >> 6, dkw = (col & 63) >> 1;
            Y[(((size_t)(bidx * HH + h) * SS + s0) << 5) + dkw]     = fppack(acc[nt][0], acc[nt][1]);
            Y[(((size_t)(bidx * HH + h) * SS + s0 + 8) << 5) + dkw] = fppack(acc[nt][2], acc[nt][3]);
        }
    }
}

// ---------------- kernel 2: fused attention (fp16 mma, 512 thr) --------------
// Pass 1 (j-tile 128): QK -> p = exp2(acc * prf*pm) -> rowsums.
// Pass 2 (j-tile 64): QK -> p = exp2(acc * prf*pm + linv) -> attn write + PV.
#define ATTN_WORDS (4608 + 4608 + 2304 + 4608 + 768)
#define ATTN_SMEM (ATTN_WORDS*4)

__global__ __launch_bounds__(512, 2) void attn_kernel(const int* __restrict__ mask,
                                                      float* __restrict__ attn) {
    extern __shared__ unsigned usm[];
    unsigned* Qh  = usm;                  // [128][36] fp16x2
    unsigned* Kh  = Qh + 4608;            // [128][36] (pass2 uses first 64 rows)
    unsigned* Vb  = Kh + 4608;            // [64 d][36 j'] transposed
    unsigned* Pb  = Vb + 2304;            // [128][36]
    float* rowsum = (float*)(Pb + 4608);  // 128
    float* linv   = rowsum + 128;         // 128  (-log2 rowsum)
    float* mrowf  = linv + 128;           // 128  (1.0 / 0.0)
    float* mcolf  = mrowf + 128;          // 128  (EXP_C / 0.0)

    const int bh = blockIdx.y, b = bh >> 3;
    const int row0 = blockIdx.x * 128;
    const int tid = threadIdx.x, lane = tid & 31, warp = tid >> 5;
    const int g = lane >> 2, t = lane & 3;
    const int wm = warp & 7, wn = warp >> 3;   // 8 x 2

    const unsigned* qbase = g_qhw + ((size_t)bh * SS << 5);
    const unsigned* kbase = g_khw + ((size_t)bh * SS << 5);
    const unsigned* vbase = g_vhw + ((size_t)bh * SS << 5);

    const int fr = tid >> 3;            // 0..63
    const int fw = (tid & 7) << 2;

    // ---- load Q tile (fp16 copy; persists across both passes) ----
    #pragma unroll
    for (int sw = 0; sw < 2; sw++) {
        int r = fr + sw * 64;
        *(uint4*)(Qh + r*36 + fw) = *(const uint4*)(qbase + ((size_t)(row0 + r) << 5) + fw);
    }
    if (tid < 128) {
        mrowf[tid] = mask[b * SS + row0 + tid] ? 1.0f : 0.0f;
        rowsum[tid] = 0.f;
    }

    float rp0 = 0.f, rp1 = 0.f;

    // ---------------- PASS 1 (j-tile 128): rowsums --------------------------
    #pragma unroll 1
    for (int j0 = 0; j0 < SS; j0 += 128) {
        __syncthreads();
        #pragma unroll
        for (int sw = 0; sw < 2; sw++) {
            int r = fr + sw * 64;
            *(uint4*)(Kh + r*36 + fw) = *(const uint4*)(kbase + ((size_t)(j0 + r) << 5) + fw);
        }
        if (tid < 128) mcolf[tid] = mask[b * SS + j0 + tid] ? EXP_C : 0.0f;
        __syncthreads();

        float acc[8][4] = {};
        #pragma unroll
        for (int s = 0; s < 4; s++) {
            int kw = s * 8;
            int r = wm * 16 + g;
            unsigned a0 = Qh[r*36 + kw + t],     a1 = Qh[(r+8)*36 + kw + t];
            unsigned a2 = Qh[r*36 + kw + t + 4], a3 = Qh[(r+8)*36 + kw + t + 4];
            #pragma unroll
            for (int nt = 0; nt < 8; nt++) {
                int c = wn * 64 + nt * 8 + g;
                unsigned b0 = Kh[c*36 + kw + t], b1 = Kh[c*36 + kw + t + 4];
                mma_fp16(acc[nt], a0, a1, a2, a3, b0, b1);
            }
        }
        const bool dtile = (j0 == row0);
        {
            int lr0 = wm * 16 + g, lr1 = lr0 + 8;
            float pr0 = mrowf[lr0], pr1 = mrowf[lr1];
            int gr0 = row0 + lr0, gr1 = row0 + lr1;
            #pragma unroll
            for (int nt = 0; nt < 8; nt++) {
                int lc = wn * 64 + nt * 8 + 2 * t;
                float pm0 = mcolf[lc], pm1 = mcolf[lc + 1];
                float f00 = pr0 * pm0, f01 = pr0 * pm1;
                float f10 = pr1 * pm0, f11 = pr1 * pm1;
                if (dtile) {
                    int gc = j0 + lc;
                    if (gr0 == gc)     f00 = EXP_C;
                    if (gr0 == gc + 1) f01 = EXP_C;
                    if (gr1 == gc)     f10 = EXP_C;
                    if (gr1 == gc + 1) f11 = EXP_C;
                }
                rp0 += fexp2(acc[nt][0] * f00) + fexp2(acc[nt][1] * f01);
                rp1 += fexp2(acc[nt][2] * f10) + fexp2(acc[nt][3] * f11);
            }
        }
    }
    {
        float s0 = rp0, s1 = rp1;
        s0 += __shfl_xor_sync(0xffffffffu, s0, 1); s0 += __shfl_xor_sync(0xffffffffu, s0, 2);
        s1 += __shfl_xor_sync(0xffffffffu, s1, 1); s1 += __shfl_xor_sync(0xffffffffu, s1, 2);
        if (t == 0) {
            atomicAdd(&rowsum[wm * 16 + g], s0);
            atomicAdd(&rowsum[wm * 16 + g + 8], s1);
        }
    }
    __syncthreads();
    if (tid < 128) linv[tid] = -flog2(rowsum[tid]);

    float oacc[4][4] = {};
    float* arow = attn + ((size_t)bh * SS + row0) * SS;

    const int vjp = tid & 31;           // j' = j/2 (0..31)
    const int vd0 = (tid >> 5) << 2;    // d block of 4 (2 words)

    // ---------------- PASS 2 (j-tile 64): attn write + PV -------------------
    #pragma unroll 1
    for (int j0 = 0; j0 < SS; j0 += 64) {
        __syncthreads();
        {
            int r = fr;     // 0..63, exactly covers the 64-row K tile
            *(uint4*)(Kh + r*36 + fw) = *(const uint4*)(kbase + ((size_t)(j0 + r) << 5) + fw);
        }
        {   // V tile transposed via PRMT: Vb[d][j'] = (v[2j'][d], v[2j'+1][d])
            uint2 ea = *(const uint2*)(vbase + ((size_t)(j0 + 2*vjp)     << 5) + (vd0 >> 1));
            uint2 eb = *(const uint2*)(vbase + ((size_t)(j0 + 2*vjp + 1) << 5) + (vd0 >> 1));
            unsigned wa[2] = {ea.x, ea.y};
            unsigned wb[2] = {eb.x, eb.y};
            #pragma unroll
            for (int i = 0; i < 2; i++) {
                Vb[(vd0 + 2*i)     * 36 + vjp] = __byte_perm(wa[i], wb[i], 0x5410);
                Vb[(vd0 + 2*i + 1) * 36 + vjp] = __byte_perm(wa[i], wb[i], 0x7632);
            }
        }
        if (tid < 64) mcolf[tid] = mask[b * SS + j0 + tid] ? EXP_C : 0.0f;
        __syncthreads();

        float acc[4][4] = {};
        #pragma unroll
        for (int s = 0; s < 4; s++) {
            int kw = s * 8;
            int r = wm * 16 + g;
            unsigned a0 = Qh[r*36 + kw + t],     a1 = Qh[(r+8)*36 + kw + t];
            unsigned a2 = Qh[r*36 + kw + t + 4], a3 = Qh[(r+8)*36 + kw + t + 4];
            #pragma unroll
            for (int nt = 0; nt < 4; nt++) {
                int c = wn * 32 + nt * 8 + g;
                unsigned b0 = Kh[c*36 + kw + t], b1 = Kh[c*36 + kw + t + 4];
                mma_fp16(acc[nt], a0, a1, a2, a3, b0, b1);
            }
        }
        const bool dtile = ((unsigned)(j0 - row0) < 128u);
        {
            int lr0 = wm * 16 + g, lr1 = lr0 + 8;
            float pr0 = mrowf[lr0], pr1 = mrowf[lr1];
            float li0 = linv[lr0], li1 = linv[lr1];
            int gr0 = row0 + lr0, gr1 = row0 + lr1;
            #pragma unroll
            for (int nt = 0; nt < 4; nt++) {
                int lc = wn * 32 + nt * 8 + 2 * t;
                float pm0 = mcolf[lc], pm1 = mcolf[lc + 1];
                float f00 = pr0 * pm0, f01 = pr0 * pm1;
                float f10 = pr1 * pm0, f11 = pr1 * pm1;
                if (dtile) {
                    int gc = j0 + lc;
                    if (gr0 == gc)     f00 = EXP_C;
                    if (gr0 == gc + 1) f01 = EXP_C;
                    if (gr1 == gc)     f10 = EXP_C;
                    if (gr1 == gc + 1) f11 = EXP_C;
                }
                float p00 = fexp2(fmaf(acc[nt][0], f00, li0));
                float p01 = fexp2(fmaf(acc[nt][1], f01, li0));
                float p10 = fexp2(fmaf(acc[nt][2], f10, li1));
                float p11 = fexp2(fmaf(acc[nt][3], f11, li1));
                int gc = j0 + lc;
                *(float2*)(arow + (size_t)lr0 * SS + gc) = make_float2(p00, p01);
                *(float2*)(arow + (size_t)lr1 * SS + gc) = make_float2(p10, p11);
                Pb[lr0 * 36 + (lc >> 1)] = fppack(p00, p01);
                Pb[lr1 * 36 + (lc >> 1)] = fppack(p10, p11);
            }
        }
        __syncthreads();
        #pragma unroll
        for (int s = 0; s < 4; s++) {
            int kw = s * 8;
            int r = wm * 16 + g;
            unsigned a0 = Pb[r*36 + kw + t],     a1 = Pb[(r+8)*36 + kw + t];
            unsigned a2 = Pb[r*36 + kw + t + 4], a3 = Pb[(r+8)*36 + kw + t + 4];
            #pragma unroll
            for (int nt = 0; nt < 4; nt++) {
                int c = wn * 32 + nt * 8 + g;
                unsigned b0 = Vb[c*36 + kw + t], b1 = Vb[c*36 + kw + t + 4];
                mma_fp16(oacc[nt], a0, a1, a2, a3, b0, b1);
            }
        }
    }
    unsigned* obase = g_ohw + (((size_t)bh * SS + row0) << 5);
    {
        int lr0 = wm * 16 + g, lr1 = lr0 + 8;
        #pragma unroll
        for (int nt = 0; nt < 4; nt++) {
            int lc = wn * 32 + nt * 8 + 2 * t;
            obase[((size_t)lr0 << 5) + (lc >> 1)] = fppack(oacc[nt][0], oacc[nt][1]);
            obase[((size_t)lr1 << 5) + (lc >> 1)] = fppack(oacc[nt][2], oacc[nt][3]);
        }
    }
}

// ---------------- kernel 3: O @ Wo + residual (fp16 mma, 512 thr) ------------
__global__ __launch_bounds__(512, 2) void out_proj_kernel(const float* __restrict__ q) {
    extern __shared__ unsigned ps[];
    unsigned* Ah = ps;              // [128][36] (O rows, head-gathered)
    unsigned* Bh = Ah + 128*36;     // [128][36] (WoT rows)

    const unsigned* WoT = g_wtw + 3 * (size_t)DD * (DD/2);

    const int row0 = blockIdx.y * 128, col0 = blockIdx.x * 128;
    const int tid = threadIdx.x, lane = tid & 31, warp = tid >> 5;
    const int g = lane >> 2, t = lane & 3;
    const int wm = warp & 7, wn = warp >> 3;

    const int bidx = row0 >> 11, srow0 = row0 & 2047;

    const int fr = tid >> 3;
    const int fw = (tid & 7) << 2;

    float acc[8][4] = {};

    for (int c = 0; c < 8; c++) {
        const int kw0 = c * 32;
        __syncthreads();
        #pragma unroll
        for (int sw = 0; sw < 2; sw++) {
            int r = fr + sw * 64;
            *(uint4*)(Ah + r*36 + fw) = *(const uint4*)(g_ohw +
                (((size_t)(bidx * HH + c) * SS + srow0 + r) << 5) + fw);
            *(uint4*)(Bh + r*36 + fw) =
                *(const uint4*)(WoT + (size_t)(col0 + r) * (DD/2) + kw0 + fw);
        }
        __syncthreads();
        #pragma unroll
        for (int s = 0; s < 4; s++) {
            const int kw = s * 8;
            int r = wm * 16 + g;
            unsigned a0 = Ah[r*36 + kw + t],     a1 = Ah[(r+8)*36 + kw + t];
            unsigned a2 = Ah[r*36 + kw + t + 4], a3 = Ah[(r+8)*36 + kw + t + 4];
            #pragma unroll
            for (int nt = 0; nt < 8; nt++) {
                int cc = wn * 64 + nt * 8 + g;
                unsigned b0 = Bh[cc*36 + kw + t], b1 = Bh[cc*36 + kw + t + 4];
                mma_fp16(acc[nt], a0, a1, a2, a3, b0, b1);
            }
        }
    }
    {
        int r0 = row0 + wm * 16 + g;
        #pragma unroll
        for (int nt = 0; nt < 8; nt++) {
            int col = col0 + wn * 64 + nt * 8 + 2 * t;
            size_t off0 = (size_t)r0 * DD + col;
            size_t off1 = (size_t)(r0 + 8) * DD + col;
            float2 q0 = *(const float2*)(q + off0);
            float2 q1 = *(const float2*)(q + off1);
            *(float2*)(g_y + off0) = make_float2(acc[nt][0] + q0.x, acc[nt][1] + q0.y);
            *(float2*)(g_y + off1) = make_float2(acc[nt][2] + q1.x, acc[nt][3] + q1.y);
        }
    }
}

// ---------------- kernel 4: LayerNorm ---------------------------------------
__global__ void ln_kernel(const float* __restrict__ gamma, const float* __restrict__ beta,
                          float* __restrict__ out) {
    const int row = blockIdx.x;
    const float* x = g_y + (size_t)row * DD;
    const int t = threadIdx.x;

    float v0 = x[t], v1 = x[t + 256];
    float s  = v0 + v1;
    float sq = v0 * v0 + v1 * v1;

    __shared__ float ssum[8], ssq[8];
    #pragma unroll
    for (int off = 16; off > 0; off >>= 1) {
        s  += __shfl_down_sync(0xffffffffu, s,  off);
        sq += __shfl_down_sync(0xffffffffu, sq, off);
    }
    if ((t & 31) == 0) { ssum[t >> 5] = s; ssq[t >> 5] = sq; }
    __syncthreads();
    if (t < 32) {
        float a = (t < 8) ? ssum[t] : 0.f;
        float b = (t < 8) ? ssq[t]  : 0.f;
        #pragma unroll
        for (int off = 4; off > 0; off >>= 1) {
            a += __shfl_down_sync(0xffffffffu, a, off);
            b += __shfl_down_sync(0xffffffffu, b, off);
        }
        if (t == 0) { ssum[0] = a; ssq[0] = b; }
    }
    __syncthreads();
    float mean = ssum[0] * (1.0f / DD);
    float var  = ssq[0]  * (1.0f / DD) - mean * mean;
    float rs   = rsqrtf(var + 1e-6f);

    out[(size_t)row * DD + t]       = (v0 - mean) * rs * gamma[t]       + beta[t];
    out[(size_t)row * DD + t + 256] = (v1 - mean) * rs * gamma[t + 256] + beta[t + 256];
}

// ---------------- launch -----------------------------------------------------
extern "C" void kernel_launch(void* const* d_in, const int* in_sizes, int n_in,
                              void* d_out, int out_size) {
    const float* q     = (const float*)d_in[0];
    const float* k     = (const float*)d_in[1];
    const float* v     = (const float*)d_in[2];
    const int*   mask  = (const int*)  d_in[3];
    const float* Wq    = (const float*)d_in[4];
    const float* Wk    = (const float*)d_in[5];
    const float* Wv    = (const float*)d_in[6];
    const float* Wo    = (const float*)d_in[7];
    const float* gamma = (const float*)d_in[8];
    const float* beta  = (const float*)d_in[9];

    float* out  = (float*)d_out;                  // [B,S,D]
    float* attn = out + (size_t)BB * SS * DD;     // [B,H,S,S]

    cudaFuncSetAttribute(attn_kernel, cudaFuncAttributeMaxDynamicSharedMemorySize, ATTN_SMEM);
    cudaFuncSetAttribute(proj_kernel, cudaFuncAttributeMaxDynamicSharedMemorySize, PJ_SMEM);
    cudaFuncSetAttribute(out_proj_kernel, cudaFuncAttributeMaxDynamicSharedMemorySize, PJ_SMEM);

    wtrans_kernel<<<dim3(16, 16, 4), 256>>>(Wq, Wk, Wv, Wo);
    proj_kernel<<<dim3(DD/128, BSN/128, 3), 512, PJ_SMEM>>>(q, k, v);
    attn_kernel<<<dim3(SS/128, BH), 512, ATTN_SMEM>>>(mask, attn);
    out_proj_kernel<<<dim3(DD/128, BSN/128), 512, PJ_SMEM>>>(q);
    ln_kernel<<<BSN, 256>>>(gamma, beta, out);
}

// round 13
// speedup vs baseline: 1.2596x; 1.2596x over previous
#include <cuda_runtime.h>
#include <cuda_fp16.h>
#include <math.h>
#include <cstdint>

#define BB 4
#define SS 2048
#define DD 512
#define HH 8
#define BH (BB*HH)
#define BSN (BB*SS)

// ---------------- scratch (device globals; fp16x2 words) --------------------
__device__ unsigned g_qhw[(size_t)BH*SS*32];   // [bh, s, 32w]
__device__ unsigned g_khw[(size_t)BH*SS*32];
__device__ unsigned g_vhw[(size_t)BH*SS*32];
__device__ unsigned g_ohw[(size_t)BH*SS*32];
__device__ unsigned g_wtw[4*(size_t)DD*(DD/2)]; // W^T fp16x2, [n][k/2]
__device__ float    g_y[(size_t)BSN*DD];

// ---------------- helpers -----------------------------------------------------
__device__ __forceinline__ unsigned fppack(float lo, float hi) {
    __half2 h = __floats2half2_rn(lo, hi);
    return *reinterpret_cast<unsigned*>(&h);
}

__device__ __forceinline__ void mma_fp16(float c[4], unsigned a0, unsigned a1,
        unsigned a2, unsigned a3, unsigned b0, unsigned b1) {
    asm("mma.sync.aligned.m16n8k16.row.col.f32.f16.f16.f32 "
        "{%0,%1,%2,%3},{%4,%5,%6,%7},{%8,%9},{%0,%1,%2,%3};"
        : "+f"(c[0]), "+f"(c[1]), "+f"(c[2]), "+f"(c[3])
        : "r"(a0), "r"(a1), "r"(a2), "r"(a3), "r"(b0), "r"(b1));
}

// ldmatrix x4: loads 4 8x8 b16 matrices; per-thread address selects rows.
__device__ __forceinline__ void ldsmx4(unsigned r[4], const unsigned* p) {
    unsigned addr = (unsigned)__cvta_generic_to_shared(p);
    asm volatile("ldmatrix.sync.aligned.m8n8.x4.shared.b16 {%0,%1,%2,%3}, [%4];"
        : "=r"(r[0]), "=r"(r[1]), "=r"(r[2]), "=r"(r[3]) : "r"(addr));
}

__device__ __forceinline__ float fexp2(float x) {
    float y;
    asm("ex2.approx.f32 %0, %1;" : "=f"(y) : "f"(x));
    return y;
}
__device__ __forceinline__ float flog2(float x) {
    float y;
    asm("lg2.approx.f32 %0, %1;" : "=f"(y) : "f"(x));
    return y;
}
#define EXP_C 0.18033688011112042f   // log2(e)/8

// A-fragment address offsets: 16 rows (lane&15), +4 words for k8-15 half
#define AROW(lane) ((lane) & 15)
#define AWOF(lane) ((((lane) >> 4) & 1) << 2)
// B-pair address offsets: 16 rows (two n-octets), +4 words for b1
#define BROW(lane) (((((lane) >> 4) & 1) << 3) + ((lane) & 7))
#define BWOF(lane) ((((lane) >> 3) & 1) << 2)

// ---------------- kernel 0: transpose W -> fp16 (Wt[n][k] = W[k][n]) --------
__global__ __launch_bounds__(256) void wtrans_kernel(const float* __restrict__ Wq,
        const float* __restrict__ Wk, const float* __restrict__ Wv,
        const float* __restrict__ Wo) {
    __shared__ float tile[32][33];
    const float* W = (blockIdx.z == 0) ? Wq : (blockIdx.z == 1) ? Wk
                   : (blockIdx.z == 2) ? Wv : Wo;
    unsigned* T = g_wtw + (size_t)blockIdx.z * DD * (DD/2);
    const int x0 = blockIdx.x * 32, y0 = blockIdx.y * 32;
    const int tx = threadIdx.x & 31, ty = threadIdx.x >> 5;   // 32 x 8
    #pragma unroll
    for (int i = 0; i < 32; i += 8)
        tile[ty + i][tx] = W[(size_t)(y0 + ty + i) * DD + x0 + tx];
    __syncthreads();
    const int wc0 = threadIdx.x & 7, xx = threadIdx.x >> 3;   // 8 wc x 32 xx
    #pragma unroll
    for (int i = 0; i < 16; i += 8) {
        int wc = wc0 + i;
        T[(size_t)(x0 + xx) * (DD/2) + (y0 >> 1) + wc] =
            fppack(tile[2*wc][xx], tile[2*wc + 1][xx]);
    }
}

// ---------------- kernel 1: QKV projection (fp16 mma + ldmatrix) -------------
#define PJ_SMEM (2*128*36*4)

__global__ __launch_bounds__(256, 2) void proj_kernel(const float* __restrict__ q,
        const float* __restrict__ k, const float* __restrict__ v) {
    extern __shared__ unsigned ps[];
    unsigned* Ah = ps;              // [128][36] fp16x2 (X rows)
    unsigned* Bh = Ah + 128*36;     // [128][36] (Wt rows = output cols)

    const float* X; unsigned* Y;
    if (blockIdx.z == 0)      { X = q; Y = g_qhw; }
    else if (blockIdx.z == 1) { X = k; Y = g_khw; }
    else                      { X = v; Y = g_vhw; }
    const unsigned* Wt = g_wtw + (size_t)blockIdx.z * DD * (DD/2);

    const int row0 = blockIdx.y * 128, col0 = blockIdx.x * 128;
    const int tid = threadIdx.x, lane = tid & 31, warp = tid >> 5;
    const int g = lane >> 2, t = lane & 3;
    const int wm = warp & 3, wn = warp >> 2;

    const int ar = AROW(lane), aw = AWOF(lane);
    const int br = BROW(lane), bw = BWOF(lane);

    const int fr = tid >> 3;            // 32 rows per sweep
    const int fcb = (tid & 7) << 3;
    const int fw = fcb >> 1;

    float acc[2][8][4] = {};

    for (int c = 0; c < 8; c++) {
        const int k0 = c * 64, kw0 = c * 32;
        __syncthreads();
        #pragma unroll
        for (int sw = 0; sw < 4; sw++) {
            int r = fr + sw * 32;
            {   // A = X rows (fp32 -> fp16)
                const float* src = X + (size_t)(row0 + r) * DD + k0 + fcb;
                float4 v0 = *(const float4*)src;
                float4 v1 = *(const float4*)(src + 4);
                *(uint4*)(Ah + r*36 + fw) = make_uint4(
                    fppack(v0.x, v0.y), fppack(v0.z, v0.w),
                    fppack(v1.x, v1.y), fppack(v1.z, v1.w));
            }
            *(uint4*)(Bh + r*36 + fw) =
                *(const uint4*)(Wt + (size_t)(col0 + r) * (DD/2) + kw0 + fw);
        }
        __syncthreads();
        #pragma unroll
        for (int s = 0; s < 4; s++) {
            const int kw = s * 8;
            unsigned a[2][4];
            #pragma unroll
            for (int mt = 0; mt < 2; mt++)
                ldsmx4(a[mt], Ah + (wm*32 + mt*16 + ar)*36 + kw + aw);
            #pragma unroll
            for (int nt = 0; nt < 8; nt += 2) {
                unsigned bb[4];
                ldsmx4(bb, Bh + (wn*64 + nt*8 + br)*36 + kw + bw);
                #pragma unroll
                for (int mt = 0; mt < 2; mt++) {
                    mma_fp16(acc[mt][nt],   a[mt][0], a[mt][1], a[mt][2], a[mt][3], bb[0], bb[1]);
                    mma_fp16(acc[mt][nt+1], a[mt][0], a[mt][1], a[mt][2], a[mt][3], bb[2], bb[3]);
                }
            }
        }
    }
    const int bidx = row0 >> 11;
    #pragma unroll
    for (int mt = 0; mt < 2; mt++) {
        int r0 = row0 + wm * 32 + mt * 16 + g;
        int s0 = r0 & 2047;
        #pragma unroll
        for (int nt = 0; nt < 8; nt++) {
            int col = col0 + wn * 64 + nt * 8 + 2 * t;
            int h = col >> 6, dkw = (col & 63) >> 1;
            Y[(((size_t)(bidx * HH + h) * SS + s0) << 5) + dkw]     = fppack(acc[mt][nt][0], acc[mt][nt][1]);
            Y[(((size_t)(bidx * HH + h) * SS + s0 + 8) << 5) + dkw] = fppack(acc[mt][nt][2], acc[mt][nt][3]);
        }
    }
}

// ---------------- kernel 2: fused attention (fp16 mma + ldmatrix) ------------
// Pass 1 (j-tile 128): QK -> p = exp2(acc * prf*pm) -> rowsums.
// Pass 2 (j-tile 64): QK -> p = exp2(acc * prf*pm + linv) -> attn write + PV.
#define ATTN_WORDS (4608 + 4608 + 2304 + 4608 + 768)
#define ATTN_SMEM (ATTN_WORDS*4)

__global__ __launch_bounds__(256, 2) void attn_kernel(const int* __restrict__ mask,
                                                      float* __restrict__ attn) {
    extern __shared__ unsigned usm[];
    unsigned* Qh  = usm;                  // [128][36] fp16x2
    unsigned* Kh  = Qh + 4608;            // [128][36] (pass2 uses first 64 rows)
    unsigned* Vb  = Kh + 4608;            // [64 d][36 j'] transposed
    unsigned* Pb  = Vb + 2304;            // [128][36]
    float* rowsum = (float*)(Pb + 4608);  // 128
    float* linv   = rowsum + 128;         // 128  (-log2 rowsum)
    float* mrowf  = linv + 128;           // 128  (1.0 / 0.0)
    float* mcolf  = mrowf + 128;          // 128  (EXP_C / 0.0)

    const int bh = blockIdx.y, b = bh >> 3;
    const int row0 = blockIdx.x * 128;
    const int tid = threadIdx.x, lane = tid & 31, warp = tid >> 5;
    const int g = lane >> 2, t = lane & 3;
    const int wm = warp & 3, wn = warp >> 2;

    const int ar = AROW(lane), aw = AWOF(lane);
    const int br = BROW(lane), bw = BWOF(lane);

    const unsigned* qbase = g_qhw + ((size_t)bh * SS << 5);
    const unsigned* kbase = g_khw + ((size_t)bh * SS << 5);
    const unsigned* vbase = g_vhw + ((size_t)bh * SS << 5);

    const int fr = tid >> 3;
    const int fw = (tid & 7) << 2;      // word offset 0..28

    // ---- load Q tile (fp16 copy; persists across both passes) ----
    #pragma unroll
    for (int sw = 0; sw < 4; sw++) {
        int r = fr + sw * 32;
        *(uint4*)(Qh + r*36 + fw) = *(const uint4*)(qbase + ((size_t)(row0 + r) << 5) + fw);
    }
    if (tid < 128) {
        mrowf[tid] = mask[b * SS + row0 + tid] ? 1.0f : 0.0f;
        rowsum[tid] = 0.f;
    }

    float rp0[2] = {0.f, 0.f};
    float rp1[2] = {0.f, 0.f};

    // ---------------- PASS 1 (j-tile 128): rowsums --------------------------
    #pragma unroll 1
    for (int j0 = 0; j0 < SS; j0 += 128) {
        __syncthreads();
        #pragma unroll
        for (int sw = 0; sw < 4; sw++) {
            int r = fr + sw * 32;
            *(uint4*)(Kh + r*36 + fw) = *(const uint4*)(kbase + ((size_t)(j0 + r) << 5) + fw);
        }
        if (tid < 128) mcolf[tid] = mask[b * SS + j0 + tid] ? EXP_C : 0.0f;
        __syncthreads();

        float acc[2][8][4] = {};
        #pragma unroll
        for (int s = 0; s < 4; s++) {
            int kw = s * 8;
            unsigned a[2][4];
            #pragma unroll
            for (int mt = 0; mt < 2; mt++)
                ldsmx4(a[mt], Qh + (wm*32 + mt*16 + ar)*36 + kw + aw);
            #pragma unroll
            for (int nt = 0; nt < 8; nt += 2) {
                unsigned bb[4];
                ldsmx4(bb, Kh + (wn*64 + nt*8 + br)*36 + kw + bw);
                #pragma unroll
                for (int mt = 0; mt < 2; mt++) {
                    mma_fp16(acc[mt][nt],   a[mt][0], a[mt][1], a[mt][2], a[mt][3], bb[0], bb[1]);
                    mma_fp16(acc[mt][nt+1], a[mt][0], a[mt][1], a[mt][2], a[mt][3], bb[2], bb[3]);
                }
            }
        }
        const bool dtile = (j0 == row0);
        #pragma unroll
        for (int mt = 0; mt < 2; mt++) {
            int lr0 = wm * 32 + mt * 16 + g, lr1 = lr0 + 8;
            float pr0 = mrowf[lr0], pr1 = mrowf[lr1];
            int gr0 = row0 + lr0, gr1 = row0 + lr1;
            #pragma unroll
            for (int nt = 0; nt < 8; nt++) {
                int lc = wn * 64 + nt * 8 + 2 * t;
                float pm0 = mcolf[lc], pm1 = mcolf[lc + 1];
                float f00 = pr0 * pm0, f01 = pr0 * pm1;
                float f10 = pr1 * pm0, f11 = pr1 * pm1;
                if (dtile) {
                    int gc = j0 + lc;
                    if (gr0 == gc)     f00 = EXP_C;
                    if (gr0 == gc + 1) f01 = EXP_C;
                    if (gr1 == gc)     f10 = EXP_C;
                    if (gr1 == gc + 1) f11 = EXP_C;
                }
                rp0[mt] += fexp2(acc[mt][nt][0] * f00) + fexp2(acc[mt][nt][1] * f01);
                rp1[mt] += fexp2(acc[mt][nt][2] * f10) + fexp2(acc[mt][nt][3] * f11);
            }
        }
    }
    #pragma unroll
    for (int mt = 0; mt < 2; mt++) {
        float s0 = rp0[mt], s1 = rp1[mt];
        s0 += __shfl_xor_sync(0xffffffffu, s0, 1); s0 += __shfl_xor_sync(0xffffffffu, s0, 2);
        s1 += __shfl_xor_sync(0xffffffffu, s1, 1); s1 += __shfl_xor_sync(0xffffffffu, s1, 2);
        if (t == 0) {
            atomicAdd(&rowsum[wm * 32 + mt * 16 + g], s0);
            atomicAdd(&rowsum[wm * 32 + mt * 16 + g + 8], s1);
        }
    }
    __syncthreads();
    if (tid < 128) linv[tid] = -flog2(rowsum[tid]);

    float oacc[2][4][4] = {};
    float* arow = attn + ((size_t)bh * SS + row0) * SS;

    const int vjp = tid & 31;           // j' = j/2
    const int vd0 = (tid >> 5) << 3;    // d block of 8 (4 words)

    // ---------------- PASS 2 (j-tile 64): attn write + PV -------------------
    #pragma unroll 1
    for (int j0 = 0; j0 < SS; j0 += 64) {
        __syncthreads();
        #pragma unroll
        for (int sw = 0; sw < 2; sw++) {
            int r = fr + sw * 32;
            *(uint4*)(Kh + r*36 + fw) = *(const uint4*)(kbase + ((size_t)(j0 + r) << 5) + fw);
        }
        {   // V tile transposed via PRMT: Vb[d][j'] = (v[2j'][d], v[2j'+1][d])
            uint4 ea = *(const uint4*)(vbase + ((size_t)(j0 + 2*vjp)     << 5) + (vd0 >> 1));
            uint4 eb = *(const uint4*)(vbase + ((size_t)(j0 + 2*vjp + 1) << 5) + (vd0 >> 1));
            unsigned wa[4] = {ea.x, ea.y, ea.z, ea.w};
            unsigned wb[4] = {eb.x, eb.y, eb.z, eb.w};
            #pragma unroll
            for (int i = 0; i < 4; i++) {
                Vb[(vd0 + 2*i)     * 36 + vjp] = __byte_perm(wa[i], wb[i], 0x5410);
                Vb[(vd0 + 2*i + 1) * 36 + vjp] = __byte_perm(wa[i], wb[i], 0x7632);
            }
        }
        if (tid < 64) mcolf[tid] = mask[b * SS + j0 + tid] ? EXP_C : 0.0f;
        __syncthreads();

        float acc[2][4][4] = {};
        #pragma unroll
        for (int s = 0; s < 4; s++) {
            int kw = s * 8;
            unsigned a[2][4];
            #pragma unroll
            for (int mt = 0; mt < 2; mt++)
                ldsmx4(a[mt], Qh + (wm*32 + mt*16 + ar)*36 + kw + aw);
            #pragma unroll
            for (int nt = 0; nt < 4; nt += 2) {
                unsigned bb[4];
                ldsmx4(bb, Kh + (wn*32 + nt*8 + br)*36 + kw + bw);
                #pragma unroll
                for (int mt = 0; mt < 2; mt++) {
                    mma_fp16(acc[mt][nt],   a[mt][0], a[mt][1], a[mt][2], a[mt][3], bb[0], bb[1]);
                    mma_fp16(acc[mt][nt+1], a[mt][0], a[mt][1], a[mt][2], a[mt][3], bb[2], bb[3]);
                }
            }
        }
        const bool dtile = ((unsigned)(j0 - row0) < 128u);
        #pragma unroll
        for (int mt = 0; mt < 2; mt++) {
            int lr0 = wm * 32 + mt * 16 + g, lr1 = lr0 + 8;
            float pr0 = mrowf[lr0], pr1 = mrowf[lr1];
            float li0 = linv[lr0], li1 = linv[lr1];
            int gr0 = row0 + lr0, gr1 = row0 + lr1;
            #pragma unroll
            for (int nt = 0; nt < 4; nt++) {
                int lc = wn * 32 + nt * 8 + 2 * t;
                float pm0 = mcolf[lc], pm1 = mcolf[lc + 1];
                float f00 = pr0 * pm0, f01 = pr0 * pm1;
                float f10 = pr1 * pm0, f11 = pr1 * pm1;
                if (dtile) {
                    int gc = j0 + lc;
                    if (gr0 == gc)     f00 = EXP_C;
                    if (gr0 == gc + 1) f01 = EXP_C;
                    if (gr1 == gc)     f10 = EXP_C;
                    if (gr1 == gc + 1) f11 = EXP_C;
                }
                float p00 = fexp2(fmaf(acc[mt][nt][0], f00, li0));
                float p01 = fexp2(fmaf(acc[mt][nt][1], f01, li0));
                float p10 = fexp2(fmaf(acc[mt][nt][2], f10, li1));
                float p11 = fexp2(fmaf(acc[mt][nt][3], f11, li1));
                int gc = j0 + lc;
                *(float2*)(arow + (size_t)lr0 * SS + gc) = make_float2(p00, p01);
                *(float2*)(arow + (size_t)lr1 * SS + gc) = make_float2(p10, p11);
                Pb[lr0 * 36 + (lc >> 1)] = fppack(p00, p01);
                Pb[lr1 * 36 + (lc >> 1)] = fppack(p10, p11);
            }
        }
        __syncthreads();
        #pragma unroll
        for (int s = 0; s < 4; s++) {
            int kw = s * 8;
            unsigned a[2][4];
            #pragma unroll
            for (int mt = 0; mt < 2; mt++)
                ldsmx4(a[mt], Pb + (wm*32 + mt*16 + ar)*36 + kw + aw);
            #pragma unroll
            for (int nt = 0; nt < 4; nt += 2) {
                unsigned bb[4];
                ldsmx4(bb, Vb + (wn*32 + nt*8 + br)*36 + kw + bw);
                #pragma unroll
                for (int mt = 0; mt < 2; mt++) {
                    mma_fp16(oacc[mt][nt],   a[mt][0], a[mt][1], a[mt][2], a[mt][3], bb[0], bb[1]);
                    mma_fp16(oacc[mt][nt+1], a[mt][0], a[mt][1], a[mt][2], a[mt][3], bb[2], bb[3]);
                }
            }
        }
    }
    unsigned* obase = g_ohw + (((size_t)bh * SS + row0) << 5);
    #pragma unroll
    for (int mt = 0; mt < 2; mt++) {
        int lr0 = wm * 32 + mt * 16 + g, lr1 = lr0 + 8;
        #pragma unroll
        for (int nt = 0; nt < 4; nt++) {
            int lc = wn * 32 + nt * 8 + 2 * t;
            obase[((size_t)lr0 << 5) + (lc >> 1)] = fppack(oacc[mt][nt][0], oacc[mt][nt][1]);
            obase[((size_t)lr1 << 5) + (lc >> 1)] = fppack(oacc[mt][nt][2], oacc[mt][nt][3]);
        }
    }
}

// ---------------- kernel 3: O @ Wo + residual (fp16 mma + ldmatrix) ----------
__global__ __launch_bounds__(256, 2) void out_proj_kernel(const float* __restrict__ q) {
    extern __shared__ unsigned ps[];
    unsigned* Ah = ps;              // [128][36] (O rows, head-gathered)
    unsigned* Bh = Ah + 128*36;     // [128][36] (WoT rows)

    const unsigned* WoT = g_wtw + 3 * (size_t)DD * (DD/2);

    const int row0 = blockIdx.y * 128, col0 = blockIdx.x * 128;
    const int tid = threadIdx.x, lane = tid & 31, warp = tid >> 5;
    const int g = lane >> 2, t = lane & 3;
    const int wm = warp & 3, wn = warp >> 2;

    const int ar = AROW(lane), aw = AWOF(lane);
    const int br = BROW(lane), bw = BWOF(lane);

    const int bidx = row0 >> 11, srow0 = row0 & 2047;

    const int fr = tid >> 3;
    const int fw = (tid & 7) << 2;

    float acc[2][8][4] = {};

    for (int c = 0; c < 8; c++) {
        const int kw0 = c * 32;
        __syncthreads();
        #pragma unroll
        for (int sw = 0; sw < 4; sw++) {
            int r = fr + sw * 32;
            *(uint4*)(Ah + r*36 + fw) = *(const uint4*)(g_ohw +
                (((size_t)(bidx * HH + c) * SS + srow0 + r) << 5) + fw);
            *(uint4*)(Bh + r*36 + fw) =
                *(const uint4*)(WoT + (size_t)(col0 + r) * (DD/2) + kw0 + fw);
        }
        __syncthreads();
        #pragma unroll
        for (int s = 0; s < 4; s++) {
            const int kw = s * 8;
            unsigned a[2][4];
            #pragma unroll
            for (int mt = 0; mt < 2; mt++)
                ldsmx4(a[mt], Ah + (wm*32 + mt*16 + ar)*36 + kw + aw);
            #pragma unroll
            for (int nt = 0; nt < 8; nt += 2) {
                unsigned bb[4];
                ldsmx4(bb, Bh + (wn*64 + nt*8 + br)*36 + kw + bw);
                #pragma unroll
                for (int mt = 0; mt < 2; mt++) {
                    mma_fp16(acc[mt][nt],   a[mt][0], a[mt][1], a[mt][2], a[mt][3], bb[0], bb[1]);
                    mma_fp16(acc[mt][nt+1], a[mt][0], a[mt][1], a[mt][2], a[mt][3], bb[2], bb[3]);
                }
            }
        }
    }
    #pragma unroll
    for (int mt = 0; mt < 2; mt++) {
        int r0 = row0 + wm * 32 + mt * 16 + g;
        #pragma unroll
        for (int nt = 0; nt < 8; nt++) {
            int col = col0 + wn * 64 + nt * 8 + 2 * t;
            size_t off0 = (size_t)r0 * DD + col;
            size_t off1 = (size_t)(r0 + 8) * DD + col;
            float2 q0 = *(const float2*)(q + off0);
            float2 q1 = *(const float2*)(q + off1);
            *(float2*)(g_y + off0) = make_float2(acc[mt][nt][0] + q0.x, acc[mt][nt][1] + q0.y);
            *(float2*)(g_y + off1) = make_float2(acc[mt][nt][2] + q1.x, acc[mt][nt][3] + q1.y);
        }
    }
}

// ---------------- kernel 4: LayerNorm ---------------------------------------
__global__ void ln_kernel(const float* __restrict__ gamma, const float* __restrict__ beta,
                          float* __restrict__ out) {
    const int row = blockIdx.x;
    const float* x = g_y + (size_t)row * DD;
    const int t = threadIdx.x;

    float v0 = x[t], v1 = x[t + 256];
    float s  = v0 + v1;
    float sq = v0 * v0 + v1 * v1;

    __shared__ float ssum[8], ssq[8];
    #pragma unroll
    for (int off = 16; off > 0; off >>= 1) {
        s  += __shfl_down_sync(0xffffffffu, s,  off);
        sq += __shfl_down_sync(0xffffffffu, sq, off);
    }
    if ((t & 31) == 0) { ssum[t >> 5] = s; ssq[t >> 5] = sq; }
    __syncthreads();
    if (t < 32) {
        float a = (t < 8) ? ssum[t] : 0.f;
        float b = (t < 8) ? ssq[t]  : 0.f;
        #pragma unroll
        for (int off = 4; off > 0; off >>= 1) {
            a += __shfl_down_sync(0xffffffffu, a, off);
            b += __shfl_down_sync(0xffffffffu, b, off);
        }
        if (t == 0) { ssum[0] = a; ssq[0] = b; }
    }
    __syncthreads();
    float mean = ssum[0] * (1.0f / DD);
    float var  = ssq[0]  * (1.0f / DD) - mean * mean;
    float rs   = rsqrtf(var + 1e-6f);

    out[(size_t)row * DD + t]       = (v0 - mean) * rs * gamma[t]       + beta[t];
    out[(size_t)row * DD + t + 256] = (v1 - mean) * rs * gamma[t + 256] + beta[t + 256];
}

// ---------------- launch -----------------------------------------------------
extern "C" void kernel_launch(void* const* d_in, const int* in_sizes, int n_in,
                              void* d_out, int out_size) {
    const float* q     = (const float*)d_in[0];
    const float* k     = (const float*)d_in[1];
    const float* v     = (const float*)d_in[2];
    const int*   mask  = (const int*)  d_in[3];
    const float* Wq    = (const float*)d_in[4];
    const float* Wk    = (const float*)d_in[5];
    const float* Wv    = (const float*)d_in[6];
    const float* Wo    = (const float*)d_in[7];
    const float* gamma = (const float*)d_in[8];
    const float* beta  = (const float*)d_in[9];

    float* out  = (float*)d_out;                  // [B,S,D]
    float* attn = out + (size_t)BB * SS * DD;     // [B,H,S,S]

    cudaFuncSetAttribute(attn_kernel, cudaFuncAttributeMaxDynamicSharedMemorySize, ATTN_SMEM);
    cudaFuncSetAttribute(proj_kernel, cudaFuncAttributeMaxDynamicSharedMemorySize, PJ_SMEM);
    cudaFuncSetAttribute(out_proj_kernel, cudaFuncAttributeMaxDynamicSharedMemorySize, PJ_SMEM);

    wtrans_kernel<<<dim3(16, 16, 4), 256>>>(Wq, Wk, Wv, Wo);
    proj_kernel<<<dim3(DD/128, BSN/128, 3), 256, PJ_SMEM>>>(q, k, v);
    attn_kernel<<<dim3(SS/128, BH), 256, ATTN_SMEM>>>(mask, attn);
    out_proj_kernel<<<dim3(DD/128, BSN/128), 256, PJ_SMEM>>>(q);
    ln_kernel<<<BSN, 256>>>(gamma, beta, out);
}